// round 10
// baseline (speedup 1.0000x reference)
#include <cuda_runtime.h>
#include <cstdint>

// Problem constants
#define Bsz 32
#define Tlen 1024
#define Idim 512
#define Hdim 512

// Scratch for the input projection (device global: no allocation allowed)
__device__ float g_xproj[(size_t)Bsz * Tlen * Hdim];  // 64 MB

// ---------------------------------------------------------------------------
// packed f32x2 helpers (FFMA2 — ptxas never auto-fuses; PTX-only)
// ---------------------------------------------------------------------------
using u64 = unsigned long long;
__device__ __forceinline__ u64 pk2(float lo, float hi) {
    u64 r; asm("mov.b64 %0,{%1,%2};" : "=l"(r) : "f"(lo), "f"(hi)); return r;
}
__device__ __forceinline__ float2 upk2(u64 v) {
    float2 f; asm("mov.b64 {%0,%1},%2;" : "=f"(f.x), "=f"(f.y) : "l"(v)); return f;
}
__device__ __forceinline__ u64 fma2(u64 a, u64 b, u64 c) {
    u64 d; asm("fma.rn.f32x2 %0,%1,%2,%3;" : "=l"(d) : "l"(a), "l"(b), "l"(c)); return d;
}
__device__ __forceinline__ u64 add2(u64 a, u64 b) {
    u64 d; asm("add.rn.f32x2 %0,%1,%2;" : "=l"(d) : "l"(a), "l"(b)); return d;
}
__device__ __forceinline__ u64 mul2(u64 a, u64 b) {
    u64 d; asm("mul.rn.f32x2 %0,%1,%2;" : "=l"(d) : "l"(a), "l"(b)); return d;
}

__device__ __forceinline__ uint32_t s2u(const void* p) {
    uint32_t a;
    asm("{ .reg .u64 t; cvta.to.shared.u64 t, %1; cvt.u32.u64 %0, t; }"
        : "=r"(a) : "l"(p));
    return a;
}
__device__ __forceinline__ uint32_t mapa_rank(uint32_t laddr, uint32_t rank) {
    uint32_t r;
    asm("mapa.shared::cluster.u32 %0, %1, %2;" : "=r"(r) : "r"(laddr), "r"(rank));
    return r;
}
__device__ __forceinline__ void mbar_init(uint32_t mb, uint32_t cnt) {
    asm volatile("mbarrier.init.shared.b64 [%0], %1;" :: "r"(mb), "r"(cnt) : "memory");
}
__device__ __forceinline__ void mbar_arrive_expect_tx(uint32_t mb, uint32_t bytes) {
    asm volatile("mbarrier.arrive.expect_tx.shared.b64 _, [%0], %1;"
                 :: "r"(mb), "r"(bytes) : "memory");
}
__device__ __forceinline__ void mbar_wait_parity(uint32_t mb, uint32_t parity) {
    asm volatile(
        "{\n\t"
        ".reg .pred P;\n\t"
        "WLOOP_%=:\n\t"
        "mbarrier.try_wait.parity.acquire.cta.shared::cta.b64 P, [%0], %1, 0x989680;\n\t"
        "@P bra.uni WDONE_%=;\n\t"
        "bra.uni WLOOP_%=;\n\t"
        "WDONE_%=:\n\t"
        "}"
        :: "r"(mb), "r"(parity) : "memory");
}
// Remote smem store with transaction accounting on the destination barrier.
// Fire-and-forget (weak); the dest mbarrier's tx count absorbs completion.
__device__ __forceinline__ void st_async_u64(uint32_t addr, u64 v, uint32_t mbar) {
    asm volatile(
        "st.async.shared::cluster.mbarrier::complete_tx::bytes.b64 [%0], %1, [%2];"
        :: "r"(addr), "l"(v), "r"(mbar) : "memory");
}
__device__ __forceinline__ void cluster_sync_asm() {
    asm volatile("barrier.cluster.arrive.aligned;" ::: "memory");
    asm volatile("barrier.cluster.wait.aligned;" ::: "memory");
}
__device__ __forceinline__ u64 shflx2(u64 v, int m) {
    float2 f = upk2(v);
    f.x = __shfl_xor_sync(0xFFFFFFFFu, f.x, m);
    f.y = __shfl_xor_sync(0xFFFFFFFFu, f.y, m);
    return pk2(f.x, f.y);
}
// Fast branch-free tanh (rel err ~1e-6, fine vs 1e-3 tolerance)
__device__ __forceinline__ float ftanh(float x) {
    float ax = fabsf(x);
    float e = __expf(-2.0f * ax);
    float r = __fdividef(1.0f - e, 1.0f + e);
    return copysignf(r, x);
}

// ---------------------------------------------------------------------------
// Kernel 1: xproj[m, h] = sum_i X[m, i] * Wih[h, i] + bih[h] + bhh[h]
//   fp32 SGEMM 128x128x16, 8x8 micro-tile, inner loop in fma.rn.f32x2
// ---------------------------------------------------------------------------
__global__ void __launch_bounds__(256) xproj_kernel(
    const float* __restrict__ X,     // [32768, 512]
    const float* __restrict__ Wih,   // [512, 512]
    const float* __restrict__ bih,
    const float* __restrict__ bhh)
{
    const int BM = 128, BN = 128, BK = 16;
    __shared__ __align__(16) float As[BK][BM + 4];
    __shared__ __align__(16) float Bs[BK][BN + 4];

    const int tid = threadIdx.x;
    const int m0 = blockIdx.y * BM;
    const int n0 = blockIdx.x * BN;
    const int tx = tid & 15;
    const int ty = tid >> 4;

    u64 acc2[8][4];
#pragma unroll
    for (int i = 0; i < 8; ++i)
#pragma unroll
        for (int j = 0; j < 4; ++j) acc2[i][j] = 0ull;

    for (int k0 = 0; k0 < Idim; k0 += BK) {
#pragma unroll
        for (int q = 0; q < 2; ++q) {
            int lin = tid + 256 * q;
            int m = lin >> 2;
            int kv = (lin & 3) << 2;
            float4 va = *(const float4*)(X + (size_t)(m0 + m) * Idim + k0 + kv);
            As[kv + 0][m] = va.x; As[kv + 1][m] = va.y;
            As[kv + 2][m] = va.z; As[kv + 3][m] = va.w;
            float4 vb = *(const float4*)(Wih + (size_t)(n0 + m) * Idim + k0 + kv);
            Bs[kv + 0][m] = vb.x; Bs[kv + 1][m] = vb.y;
            Bs[kv + 2][m] = vb.z; Bs[kv + 3][m] = vb.w;
        }
        __syncthreads();

#pragma unroll
        for (int kk = 0; kk < BK; ++kk) {
            float ra[8];
            *(float4*)&ra[0] = *(const float4*)&As[kk][ty * 8];
            *(float4*)&ra[4] = *(const float4*)&As[kk][ty * 8 + 4];
            ulonglong2 rbA = *(const ulonglong2*)&Bs[kk][tx * 8];
            ulonglong2 rbB = *(const ulonglong2*)&Bs[kk][tx * 8 + 4];
            u64 rb2[4] = { rbA.x, rbA.y, rbB.x, rbB.y };
#pragma unroll
            for (int i = 0; i < 8; ++i) {
                u64 rap = pk2(ra[i], ra[i]);
#pragma unroll
                for (int j = 0; j < 4; ++j)
                    acc2[i][j] = fma2(rap, rb2[j], acc2[i][j]);
            }
        }
        __syncthreads();
    }

    u64 bs2[4];
#pragma unroll
    for (int j = 0; j < 4; ++j) {
        float blo = bih[n0 + tx * 8 + 2 * j] + bhh[n0 + tx * 8 + 2 * j];
        float bhi = bih[n0 + tx * 8 + 2 * j + 1] + bhh[n0 + tx * 8 + 2 * j + 1];
        bs2[j] = pk2(blo, bhi);
    }

#pragma unroll
    for (int i = 0; i < 8; ++i) {
        float2 p0 = upk2(add2(acc2[i][0], bs2[0]));
        float2 p1 = upk2(add2(acc2[i][1], bs2[1]));
        float2 p2 = upk2(add2(acc2[i][2], bs2[2]));
        float2 p3 = upk2(add2(acc2[i][3], bs2[3]));
        float* crow = g_xproj + (size_t)(m0 + ty * 8 + i) * Hdim + n0 + tx * 8;
        *(float4*)(crow)     = make_float4(p0.x, p0.y, p1.x, p1.y);
        *(float4*)(crow + 4) = make_float4(p2.x, p2.y, p3.x, p3.y);
    }
}

// ---------------------------------------------------------------------------
// Kernel 2: the recurrence — all-to-all of M-partials (round-9 structure:
//   the measured best). ONE isolated change: the exchange uses per-lane
//   st.async.shared::cluster.mbarrier::complete_tx::bytes stores straight
//   from registers instead of staging + fence + cp.async.bulk engine. Same
//   destination layout, same swizzle, same barriers (count 1, expect 7*512,
//   double-buffered, tid0 re-arm), same gather. Removes the staging STS,
//   syncwarp, proxy fence, and engine queue/fetch latency from the step.
// ---------------------------------------------------------------------------
__global__ void __launch_bounds__(256, 1) __cluster_dims__(8, 1, 1)
rnn_kernel(const float* __restrict__ Whh,   // [512, 512]
           const float* __restrict__ kern,  // [4]
           float* __restrict__ out_states,  // [B, T, H]
           float* __restrict__ out_last)    // [B, H]
{
    __shared__ __align__(16) float arr[2][8][128];    // 8KB [slot][src][swz 512B]
    __shared__ __align__(16) float hloc[2][64];       // h_t[own rows], batch-major
    __shared__ __align__(16) float xs[2][2][8][64];   // 8KB xproj stage
    __shared__ __align__(16) float xout[2][2][8][64]; // 8KB output stage (dbuf)
    __shared__ __align__(8)  u64 mbars[2];

    const int tid   = threadIdx.x;
    const int lane  = tid & 31;
    const int w     = tid >> 5;            // warp id == destination peer
    const int slice = blockIdx.x;          // cluster rank 0..7
    const int grp   = blockIdx.y;          // 0..15
    const int b0    = grp * 2;

    // Register weights: rows 64w+2*lane, +1 of Whh, columns [64*slice, +64),
    // packed along K (pairs of adjacent columns).
    u64 wR0[32], wR1[32];
    {
        const float* r0p = Whh + (size_t)(64 * w + 2 * lane) * Hdim + 64 * slice;
        const float* r1p = r0p + Hdim;
#pragma unroll
        for (int m = 0; m < 16; ++m) {
            ulonglong2 u0 = *(const ulonglong2*)(r0p + 4 * m);
            ulonglong2 u1 = *(const ulonglong2*)(r1p + 4 * m);
            wR0[2 * m] = u0.x; wR0[2 * m + 1] = u0.y;
            wR1[2 * m] = u1.x; wR1[2 * m + 1] = u1.y;
        }
    }
    const u64 kk0 = pk2(kern[0], kern[0]), kk1 = pk2(kern[1], kern[1]);
    const u64 kk2 = pk2(kern[2], kern[2]), kk3 = pk2(kern[3], kern[3]);

    // Init + arm tx-barriers (count 1, expect 7*512 B per slot)
    const uint32_t mb0 = s2u(&mbars[0]);
    if (tid == 0) {
        mbar_init(mb0, 1);
        mbar_init(mb0 + 8, 1);
        mbar_arrive_expect_tx(mb0, 7 * 512);
        mbar_arrive_expect_tx(mb0 + 8, 7 * 512);
    }

    // Per-lane remote targets on peer w: this CTA's src block, own swizzle slot
    const uint32_t arr_b = s2u(arr);
    const uint32_t rdst  = mapa_rank(arr_b, w)
                         + (uint32_t)(slice * 512 + ((lane + 5 * slice) & 31) * 16);
    const uint32_t rbar  = mapa_rank(mb0, w);

    cluster_sync_asm();   // barrier init visible cluster-wide

    // xproj staging: one float4 per thread per 8-step group
    const int pb  = tid >> 7;
    const int pt  = (tid >> 4) & 7;
    const int pu  = tid & 15;
    const float* xsrc = g_xproj + (size_t)(b0 + pb) * Tlen * Hdim
                        + (size_t)pt * Hdim + slice * 64 + pu * 4;
    *(float4*)&xs[0][pb][pt][pu * 4] = *(const float4*)(xsrc);        // group 0
    float4 xpre = *(const float4*)(xsrc + 8 * Hdim);                  // group 1
    __syncthreads();

    // Phase-A roles: thread -> (row, quad); quad handles source pair 2q,2q+1
    const int row  = tid >> 2;     // 0..63 (own-row index)
    const int quad = tid & 3;

    // Register M-ring: M_{t-2}, M_{t-3}, M_{t-4} for this row, packed (b0,b1)
    u64 ring0 = 0ull, ring1 = 0ull, ring2 = 0ull;

    const char* arrc = (const char*)arr;

    for (int t = 0; t < Tlen; ++t) {
        // ---- Gap fillers BEFORE the wait: staging + output flush ----
        if ((t & 7) == 0) {
            int g = t >> 3;
            // Stage xproj group g+1 into the idle buffer
            *(float4*)&xs[(g + 1) & 1][pb][pt][pu * 4] = xpre;
            if (t + 16 < Tlen)
                xpre = *(const float4*)(xsrc + (size_t)(t + 16) * Hdim);
            // Flush the previous output group (written through step t-1;
            // ordered by step t-1's phase A->B syncthreads)
            if (t > 0) {
                *(float4*)(out_states + (size_t)(b0 + pb) * Tlen * Hdim
                           + (size_t)(t - 8 + pt) * Hdim + slice * 64 + pu * 4)
                    = *(const float4*)&xout[(g - 1) & 1][pb][pt][pu * 4];
            }
        }

        // ---- Phase A: wait, gather M_{t-1}, taps, tanh -> h_t (own rows) ----
        u64 Mt1 = 0ull;
        if (t > 0) {
            const uint32_t bar = mb0 + ((t - 1) & 1) * 8;
            mbar_wait_parity(bar, ((t - 1) >> 1) & 1);
            if (tid == 0)
                mbar_arrive_expect_tx(bar, 7 * 512);   // re-arm for step t+1

            const char* ab = arrc + ((t - 1) & 1) * 4096;
            const int s0 = 2 * quad, s1 = 2 * quad + 1;
            const int pbk = row >> 1, rb = (row & 1) * 8;
            u64 v0 = *(const u64*)(ab + s0 * 512 + (((pbk + 5 * s0) & 31) * 16 + rb));
            u64 v1 = *(const u64*)(ab + s1 * 512 + (((pbk + 5 * s1) & 31) * 16 + rb));
            u64 m = add2(v0, v1);
            m = add2(m, shflx2(m, 1));
            m = add2(m, shflx2(m, 2));
            Mt1 = m;                       // all 4 quad lanes hold full M[row]
        }

        // 4-tap Lagrange on the register M-ring
        u64 rr = fma2(kk0, Mt1, fma2(kk1, ring0, fma2(kk2, ring1, mul2(kk3, ring2))));
        ring2 = ring1; ring1 = ring0; ring0 = Mt1;

        if (quad < 2) {                    // quad == batch
            float2 rf = upk2(rr);
            float pre = (quad == 0) ? rf.x : rf.y;
            float val = ftanh(pre + xs[(t >> 3) & 1][quad][t & 7][row]);
            hloc[quad][row] = val;
            xout[(t >> 3) & 1][quad][t & 7][row] = val;
            if (t == Tlen - 1)
                out_last[(size_t)(b0 + quad) * Hdim + slice * 64 + row] = val;
        }

        __syncthreads();   // hloc/xout ready; xs stage ordered

        // ---- Phase B: per-warp partial chunk GEMV + direct st.async send ----
        if (t < Tlen - 1) {
            u64 aA0 = 0ull, cA0 = 0ull, aA1 = 0ull, cA1 = 0ull;
            u64 aB0 = 0ull, cB0 = 0ull, aB1 = 0ull, cB1 = 0ull;
#pragma unroll
            for (int m = 0; m < 16; ++m) {
                ulonglong2 h0 = *(const ulonglong2*)&hloc[0][4 * m];
                ulonglong2 h1 = *(const ulonglong2*)&hloc[1][4 * m];
                aA0 = fma2(wR0[2 * m],     h0.x, aA0);
                cA0 = fma2(wR0[2 * m + 1], h0.y, cA0);
                aA1 = fma2(wR0[2 * m],     h1.x, aA1);
                cA1 = fma2(wR0[2 * m + 1], h1.y, cA1);
                aB0 = fma2(wR1[2 * m],     h0.x, aB0);
                cB0 = fma2(wR1[2 * m + 1], h0.y, cB0);
                aB1 = fma2(wR1[2 * m],     h1.x, aB1);
                cB1 = fma2(wR1[2 * m + 1], h1.y, cB1);
            }
            float2 fA0 = upk2(add2(aA0, cA0));
            float2 fA1 = upk2(add2(aA1, cA1));
            float2 fB0 = upk2(add2(aB0, cB0));
            float2 fB1 = upk2(add2(aB1, cB1));
            // rows 2*lane, 2*lane+1 of chunk w; (r0b0,r0b1) , (r1b0,r1b1)
            u64 oA = pk2(fA0.x + fA0.y, fA1.x + fA1.y);
            u64 oB = pk2(fB0.x + fB0.y, fB1.x + fB1.y);

            if (w == slice) {
                // own chunk: local STS, covered by end-of-step syncthreads
                float* dstp = &arr[t & 1][slice][((lane + 5 * slice) & 31) * 4];
                *(u64*)(dstp)     = oA;
                *(u64*)(dstp + 2) = oB;
            } else {
                // remote chunk: fire-and-forget with tx accounting
                const uint32_t a = rdst + (uint32_t)((t & 1) * 4096);
                const uint32_t b = rbar + (uint32_t)((t & 1) * 8);
                st_async_u64(a,     oA, b);
                st_async_u64(a + 8, oB, b);
            }
        }

        __syncthreads();   // own-chunk STS + xout ordering for next step
    }

    // Final output group (t = 1016..1023, buffer 1)
    *(float4*)(out_states + (size_t)(b0 + pb) * Tlen * Hdim
               + (size_t)(Tlen - 8 + pt) * Hdim + slice * 64 + pu * 4)
        = *(const float4*)&xout[1][pb][pt][pu * 4];

    // No CTA may exit while peers' remote stores could still target it
    cluster_sync_asm();
}

// ---------------------------------------------------------------------------
extern "C" void kernel_launch(void* const* d_in, const int* in_sizes, int n_in,
                              void* d_out, int out_size)
{
    (void)in_sizes; (void)n_in; (void)out_size;
    const float* x    = (const float*)d_in[0];   // [32, 1024, 512]
    const float* Wih  = (const float*)d_in[1];   // [512, 512]
    const float* Whh  = (const float*)d_in[2];   // [512, 512]
    const float* bih  = (const float*)d_in[3];   // [512]
    const float* bhh  = (const float*)d_in[4];   // [512]
    const float* kern = (const float*)d_in[5];   // [4]

    float* out        = (float*)d_out;
    float* out_states = out;                                   // [32,1024,512]
    float* out_last   = out + (size_t)Bsz * Tlen * Hdim;       // [32,512]

    dim3 gg(Hdim / 128, (Bsz * Tlen) / 128);   // (4, 256)
    xproj_kernel<<<gg, 256>>>(x, Wih, bih, bhh);

    dim3 gr(8, 16);
    rnn_kernel<<<gr, 256>>>(Whh, kern, out_states, out_last);
}

// round 11
// speedup vs baseline: 1.2564x; 1.2564x over previous
#include <cuda_runtime.h>
#include <cstdint>

// Problem constants
#define Bsz 32
#define Tlen 1024
#define Idim 512
#define Hdim 512

// Scratch for the input projection (device global: no allocation allowed)
__device__ float g_xproj[(size_t)Bsz * Tlen * Hdim];  // 64 MB

// ---------------------------------------------------------------------------
// packed f32x2 helpers (FFMA2 — ptxas never auto-fuses; PTX-only)
// ---------------------------------------------------------------------------
using u64 = unsigned long long;
__device__ __forceinline__ u64 pk2(float lo, float hi) {
    u64 r; asm("mov.b64 %0,{%1,%2};" : "=l"(r) : "f"(lo), "f"(hi)); return r;
}
__device__ __forceinline__ float2 upk2(u64 v) {
    float2 f; asm("mov.b64 {%0,%1},%2;" : "=f"(f.x), "=f"(f.y) : "l"(v)); return f;
}
__device__ __forceinline__ u64 fma2(u64 a, u64 b, u64 c) {
    u64 d; asm("fma.rn.f32x2 %0,%1,%2,%3;" : "=l"(d) : "l"(a), "l"(b), "l"(c)); return d;
}
__device__ __forceinline__ u64 add2(u64 a, u64 b) {
    u64 d; asm("add.rn.f32x2 %0,%1,%2;" : "=l"(d) : "l"(a), "l"(b)); return d;
}
__device__ __forceinline__ u64 mul2(u64 a, u64 b) {
    u64 d; asm("mul.rn.f32x2 %0,%1,%2;" : "=l"(d) : "l"(a), "l"(b)); return d;
}

__device__ __forceinline__ uint32_t s2u(const void* p) {
    uint32_t a;
    asm("{ .reg .u64 t; cvta.to.shared.u64 t, %1; cvt.u32.u64 %0, t; }"
        : "=r"(a) : "l"(p));
    return a;
}
__device__ __forceinline__ uint32_t mapa_rank(uint32_t laddr, uint32_t rank) {
    uint32_t r;
    asm("mapa.shared::cluster.u32 %0, %1, %2;" : "=r"(r) : "r"(laddr), "r"(rank));
    return r;
}
__device__ __forceinline__ void mbar_init(uint32_t mb, uint32_t cnt) {
    asm volatile("mbarrier.init.shared.b64 [%0], %1;" :: "r"(mb), "r"(cnt) : "memory");
}
__device__ __forceinline__ void mbar_arrive_expect_tx(uint32_t mb, uint32_t bytes) {
    asm volatile("mbarrier.arrive.expect_tx.shared.b64 _, [%0], %1;"
                 :: "r"(mb), "r"(bytes) : "memory");
}
__device__ __forceinline__ void mbar_wait_parity(uint32_t mb, uint32_t parity) {
    asm volatile(
        "{\n\t"
        ".reg .pred P;\n\t"
        "WLOOP_%=:\n\t"
        "mbarrier.try_wait.parity.acquire.cta.shared::cta.b64 P, [%0], %1, 0x989680;\n\t"
        "@P bra.uni WDONE_%=;\n\t"
        "bra.uni WLOOP_%=;\n\t"
        "WDONE_%=:\n\t"
        "}"
        :: "r"(mb), "r"(parity) : "memory");
}
__device__ __forceinline__ void bulk_dsmem(uint32_t dst, uint32_t src,
                                           uint32_t bytes, uint32_t rembar) {
    asm volatile(
        "cp.async.bulk.shared::cluster.shared::cta.mbarrier::complete_tx::bytes "
        "[%0], [%1], %2, [%3];"
        :: "r"(dst), "r"(src), "r"(bytes), "r"(rembar) : "memory");
}
__device__ __forceinline__ void fence_proxy_async_cta() {
    asm volatile("fence.proxy.async.shared::cta;" ::: "memory");
}
__device__ __forceinline__ void cluster_sync_asm() {
    asm volatile("barrier.cluster.arrive.aligned;" ::: "memory");
    asm volatile("barrier.cluster.wait.aligned;" ::: "memory");
}
__device__ __forceinline__ u64 shflx2(u64 v, int m) {
    float2 f = upk2(v);
    f.x = __shfl_xor_sync(0xFFFFFFFFu, f.x, m);
    f.y = __shfl_xor_sync(0xFFFFFFFFu, f.y, m);
    return pk2(f.x, f.y);
}
// Fast branch-free tanh (rel err ~1e-6, fine vs 1e-3 tolerance)
__device__ __forceinline__ float ftanh(float x) {
    float ax = fabsf(x);
    float e = __expf(-2.0f * ax);
    float r = __fdividef(1.0f - e, 1.0f + e);
    return copysignf(r, x);
}

// ---------------------------------------------------------------------------
// Kernel 1: xproj[m, h] = sum_i X[m, i] * Wih[h, i] + bih[h] + bhh[h]
//   fp32 SGEMM 128x128x16, 8x8 micro-tile, fma.rn.f32x2 inner loop,
//   DOUBLE-BUFFERED smem: next tile's LDG issued before compute, STS into
//   the alternate buffer after compute, one __syncthreads per iteration —
//   global-load latency fully hidden behind the tile's FMA work.
// ---------------------------------------------------------------------------
__global__ void __launch_bounds__(256) xproj_kernel(
    const float* __restrict__ X,     // [32768, 512]
    const float* __restrict__ Wih,   // [512, 512]
    const float* __restrict__ bih,
    const float* __restrict__ bhh)
{
    const int BM = 128, BN = 128, BK = 16;
    __shared__ __align__(16) float As[2][BK][BM + 4];
    __shared__ __align__(16) float Bs[2][BK][BN + 4];

    const int tid = threadIdx.x;
    const int m0 = blockIdx.y * BM;
    const int n0 = blockIdx.x * BN;
    const int tx = tid & 15;
    const int ty = tid >> 4;

    // Loader mapping: q in {0,1}; lin = tid + 256q covers 512 float4 slots
    int lm[2], lkv[2];
#pragma unroll
    for (int q = 0; q < 2; ++q) {
        int lin = tid + 256 * q;
        lm[q]  = lin >> 2;            // 0..127 row within tile
        lkv[q] = (lin & 3) << 2;      // 0,4,8,12 k-offset
    }

    float4 pa[2], pb[2];              // prefetch registers

    // Prologue: load tile 0
#pragma unroll
    for (int q = 0; q < 2; ++q) {
        pa[q] = *(const float4*)(X   + (size_t)(m0 + lm[q]) * Idim + lkv[q]);
        pb[q] = *(const float4*)(Wih + (size_t)(n0 + lm[q]) * Idim + lkv[q]);
    }
#pragma unroll
    for (int q = 0; q < 2; ++q) {
        As[0][lkv[q] + 0][lm[q]] = pa[q].x; As[0][lkv[q] + 1][lm[q]] = pa[q].y;
        As[0][lkv[q] + 2][lm[q]] = pa[q].z; As[0][lkv[q] + 3][lm[q]] = pa[q].w;
        Bs[0][lkv[q] + 0][lm[q]] = pb[q].x; Bs[0][lkv[q] + 1][lm[q]] = pb[q].y;
        Bs[0][lkv[q] + 2][lm[q]] = pb[q].z; Bs[0][lkv[q] + 3][lm[q]] = pb[q].w;
    }
    __syncthreads();

    u64 acc2[8][4];
#pragma unroll
    for (int i = 0; i < 8; ++i)
#pragma unroll
        for (int j = 0; j < 4; ++j) acc2[i][j] = 0ull;

    for (int k0 = 0; k0 < Idim; k0 += BK) {
        const int p = (k0 >> 4) & 1;
        const bool more = (k0 + BK < Idim);

        // Prefetch next tile into registers (latency overlapped with compute)
        if (more) {
#pragma unroll
            for (int q = 0; q < 2; ++q) {
                pa[q] = *(const float4*)(X   + (size_t)(m0 + lm[q]) * Idim + k0 + BK + lkv[q]);
                pb[q] = *(const float4*)(Wih + (size_t)(n0 + lm[q]) * Idim + k0 + BK + lkv[q]);
            }
        }

        // Compute on buffer p
#pragma unroll
        for (int kk = 0; kk < BK; ++kk) {
            float ra[8];
            *(float4*)&ra[0] = *(const float4*)&As[p][kk][ty * 8];
            *(float4*)&ra[4] = *(const float4*)&As[p][kk][ty * 8 + 4];
            ulonglong2 rbA = *(const ulonglong2*)&Bs[p][kk][tx * 8];
            ulonglong2 rbB = *(const ulonglong2*)&Bs[p][kk][tx * 8 + 4];
            u64 rb2[4] = { rbA.x, rbA.y, rbB.x, rbB.y };
#pragma unroll
            for (int i = 0; i < 8; ++i) {
                u64 rap = pk2(ra[i], ra[i]);
#pragma unroll
                for (int j = 0; j < 4; ++j)
                    acc2[i][j] = fma2(rap, rb2[j], acc2[i][j]);
            }
        }

        // Stage the prefetched tile into the alternate buffer
        if (more) {
            const int n = p ^ 1;
#pragma unroll
            for (int q = 0; q < 2; ++q) {
                As[n][lkv[q] + 0][lm[q]] = pa[q].x; As[n][lkv[q] + 1][lm[q]] = pa[q].y;
                As[n][lkv[q] + 2][lm[q]] = pa[q].z; As[n][lkv[q] + 3][lm[q]] = pa[q].w;
                Bs[n][lkv[q] + 0][lm[q]] = pb[q].x; Bs[n][lkv[q] + 1][lm[q]] = pb[q].y;
                Bs[n][lkv[q] + 2][lm[q]] = pb[q].z; Bs[n][lkv[q] + 3][lm[q]] = pb[q].w;
            }
            __syncthreads();
        }
    }

    u64 bs2[4];
#pragma unroll
    for (int j = 0; j < 4; ++j) {
        float blo = bih[n0 + tx * 8 + 2 * j] + bhh[n0 + tx * 8 + 2 * j];
        float bhi = bih[n0 + tx * 8 + 2 * j + 1] + bhh[n0 + tx * 8 + 2 * j + 1];
        bs2[j] = pk2(blo, bhi);
    }

#pragma unroll
    for (int i = 0; i < 8; ++i) {
        float2 p0 = upk2(add2(acc2[i][0], bs2[0]));
        float2 p1 = upk2(add2(acc2[i][1], bs2[1]));
        float2 p2 = upk2(add2(acc2[i][2], bs2[2]));
        float2 p3 = upk2(add2(acc2[i][3], bs2[3]));
        float* crow = g_xproj + (size_t)(m0 + ty * 8 + i) * Hdim + n0 + tx * 8;
        *(float4*)(crow)     = make_float4(p0.x, p0.y, p1.x, p1.y);
        *(float4*)(crow + 4) = make_float4(p2.x, p2.y, p3.x, p3.y);
    }
}

// ---------------------------------------------------------------------------
// Kernel 2: the recurrence — all-to-all of M-partials via bulk DSMEM engine.
//   BYTE-IDENTICAL to round 9 (the measured best across all exchange
//   mechanisms tried: cluster.sync, release-arrive, bulk engine, st.async).
// ---------------------------------------------------------------------------
__global__ void __launch_bounds__(256, 1) __cluster_dims__(8, 1, 1)
rnn_kernel(const float* __restrict__ Whh,   // [512, 512]
           const float* __restrict__ kern,  // [4]
           float* __restrict__ out_states,  // [B, T, H]
           float* __restrict__ out_last)    // [B, H]
{
    __shared__ __align__(16) float arr[2][8][128];    // 8KB [slot][src][swz 512B]
    __shared__ __align__(16) float stg[2][8][128];    // 8KB [slot][warp][512B]
    __shared__ __align__(16) float hloc[2][64];       // h_t[own rows], batch-major
    __shared__ __align__(16) float xs[2][2][8][64];   // 8KB xproj stage
    __shared__ __align__(16) float xout[2][2][8][64]; // 8KB output stage (dbuf)
    __shared__ __align__(8)  u64 mbars[2];

    const int tid   = threadIdx.x;
    const int lane  = tid & 31;
    const int w     = tid >> 5;            // warp id == destination peer
    const int slice = blockIdx.x;          // cluster rank 0..7
    const int grp   = blockIdx.y;          // 0..15
    const int b0    = grp * 2;

    // Register weights: rows 64w+2*lane, +1 of Whh, columns [64*slice, +64),
    // packed along K (pairs of adjacent columns).
    u64 wR0[32], wR1[32];
    {
        const float* r0p = Whh + (size_t)(64 * w + 2 * lane) * Hdim + 64 * slice;
        const float* r1p = r0p + Hdim;
#pragma unroll
        for (int m = 0; m < 16; ++m) {
            ulonglong2 u0 = *(const ulonglong2*)(r0p + 4 * m);
            ulonglong2 u1 = *(const ulonglong2*)(r1p + 4 * m);
            wR0[2 * m] = u0.x; wR0[2 * m + 1] = u0.y;
            wR1[2 * m] = u1.x; wR1[2 * m + 1] = u1.y;
        }
    }
    const u64 kk0 = pk2(kern[0], kern[0]), kk1 = pk2(kern[1], kern[1]);
    const u64 kk2 = pk2(kern[2], kern[2]), kk3 = pk2(kern[3], kern[3]);

    // Init + arm tx-barriers (count 1, expect 7*512 B per slot)
    const uint32_t mb0 = s2u(&mbars[0]);
    if (tid == 0) {
        mbar_init(mb0, 1);
        mbar_init(mb0 + 8, 1);
        mbar_arrive_expect_tx(mb0, 7 * 512);
        mbar_arrive_expect_tx(mb0 + 8, 7 * 512);
    }

    // Per-warp remote targets (peer w): its arr slot at src index = MY slice
    const uint32_t arr_b = s2u(arr);
    const uint32_t dst_b = mapa_rank(arr_b, w) + (uint32_t)(slice * 512);
    const uint32_t bar_b = mapa_rank(mb0, w);

    cluster_sync_asm();   // barrier init visible cluster-wide

    // xproj staging: one float4 per thread per 8-step group
    const int pb  = tid >> 7;
    const int pt  = (tid >> 4) & 7;
    const int pu  = tid & 15;
    const float* xsrc = g_xproj + (size_t)(b0 + pb) * Tlen * Hdim
                        + (size_t)pt * Hdim + slice * 64 + pu * 4;
    *(float4*)&xs[0][pb][pt][pu * 4] = *(const float4*)(xsrc);        // group 0
    float4 xpre = *(const float4*)(xsrc + 8 * Hdim);                  // group 1
    __syncthreads();

    // Phase-A roles: thread -> (row, quad); quad handles source pair 2q,2q+1
    const int row  = tid >> 2;     // 0..63 (own-row index)
    const int quad = tid & 3;

    // Register M-ring: M_{t-2}, M_{t-3}, M_{t-4} for this row, packed (b0,b1)
    u64 ring0 = 0ull, ring1 = 0ull, ring2 = 0ull;

    const char* arrc = (const char*)arr;

    for (int t = 0; t < Tlen; ++t) {
        // ---- Gap fillers BEFORE the wait: staging + output flush ----
        if ((t & 7) == 0) {
            int g = t >> 3;
            // Stage xproj group g+1 into the idle buffer
            *(float4*)&xs[(g + 1) & 1][pb][pt][pu * 4] = xpre;
            if (t + 16 < Tlen)
                xpre = *(const float4*)(xsrc + (size_t)(t + 16) * Hdim);
            // Flush the previous output group (written through step t-1;
            // ordered by step t-1's phase A->B syncthreads)
            if (t > 0) {
                *(float4*)(out_states + (size_t)(b0 + pb) * Tlen * Hdim
                           + (size_t)(t - 8 + pt) * Hdim + slice * 64 + pu * 4)
                    = *(const float4*)&xout[(g - 1) & 1][pb][pt][pu * 4];
            }
        }

        // ---- Phase A: wait, gather M_{t-1}, taps, tanh -> h_t (own rows) ----
        u64 Mt1 = 0ull;
        if (t > 0) {
            const uint32_t bar = mb0 + ((t - 1) & 1) * 8;
            mbar_wait_parity(bar, ((t - 1) >> 1) & 1);
            if (tid == 0)
                mbar_arrive_expect_tx(bar, 7 * 512);   // re-arm for step t+1

            const char* ab = arrc + ((t - 1) & 1) * 4096;
            const int s0 = 2 * quad, s1 = 2 * quad + 1;
            const int pbk = row >> 1, rb = (row & 1) * 8;
            u64 v0 = *(const u64*)(ab + s0 * 512 + (((pbk + 5 * s0) & 31) * 16 + rb));
            u64 v1 = *(const u64*)(ab + s1 * 512 + (((pbk + 5 * s1) & 31) * 16 + rb));
            u64 m = add2(v0, v1);
            m = add2(m, shflx2(m, 1));
            m = add2(m, shflx2(m, 2));
            Mt1 = m;                       // all 4 quad lanes hold full M[row]
        }

        // 4-tap Lagrange on the register M-ring
        u64 rr = fma2(kk0, Mt1, fma2(kk1, ring0, fma2(kk2, ring1, mul2(kk3, ring2))));
        ring2 = ring1; ring1 = ring0; ring0 = Mt1;

        if (quad < 2) {                    // quad == batch
            float2 rf = upk2(rr);
            float pre = (quad == 0) ? rf.x : rf.y;
            float val = ftanh(pre + xs[(t >> 3) & 1][quad][t & 7][row]);
            hloc[quad][row] = val;
            xout[(t >> 3) & 1][quad][t & 7][row] = val;
            if (t == Tlen - 1)
                out_last[(size_t)(b0 + quad) * Hdim + slice * 64 + row] = val;
        }

        __syncthreads();   // hloc/xout ready; xs stage ordered

        // ---- Phase B: per-warp partial chunk GEMV + immediate send ----
        if (t < Tlen - 1) {
            u64 aA0 = 0ull, cA0 = 0ull, aA1 = 0ull, cA1 = 0ull;
            u64 aB0 = 0ull, cB0 = 0ull, aB1 = 0ull, cB1 = 0ull;
#pragma unroll
            for (int m = 0; m < 16; ++m) {
                ulonglong2 h0 = *(const ulonglong2*)&hloc[0][4 * m];
                ulonglong2 h1 = *(const ulonglong2*)&hloc[1][4 * m];
                aA0 = fma2(wR0[2 * m],     h0.x, aA0);
                cA0 = fma2(wR0[2 * m + 1], h0.y, cA0);
                aA1 = fma2(wR0[2 * m],     h1.x, aA1);
                cA1 = fma2(wR0[2 * m + 1], h1.y, cA1);
                aB0 = fma2(wR1[2 * m],     h0.x, aB0);
                cB0 = fma2(wR1[2 * m + 1], h0.y, cB0);
                aB1 = fma2(wR1[2 * m],     h1.x, aB1);
                cB1 = fma2(wR1[2 * m + 1], h1.y, cB1);
            }
            float2 fA0 = upk2(add2(aA0, cA0));
            float2 fA1 = upk2(add2(aA1, cA1));
            float2 fB0 = upk2(add2(aB0, cB0));
            float2 fB1 = upk2(add2(aB1, cB1));
            // rows 2*lane, 2*lane+1 of chunk w; values (r0b0,r0b1,r1b0,r1b1)
            float4 o = make_float4(fA0.x + fA0.y, fA1.x + fA1.y,
                                   fB0.x + fB0.y, fB1.x + fB1.y);
            float* dstp = (w == slice) ? &arr[t & 1][slice][0]
                                       : &stg[t & 1][w][0];
            *(float4*)(dstp + ((lane + 5 * slice) & 31) * 4) = o;
            __syncwarp();
            if (w != slice && lane == 0) {
                fence_proxy_async_cta();
                bulk_dsmem(dst_b + (uint32_t)((t & 1) * 4096),
                           s2u(&stg[t & 1][w][0]), 512,
                           bar_b + (uint32_t)((t & 1) * 8));
            }
        }

        __syncthreads();   // own-chunk STS visible to next step's gather
    }

    // Final output group (t = 1016..1023, buffer (127)&1 = 1)
    *(float4*)(out_states + (size_t)(b0 + pb) * Tlen * Hdim
               + (size_t)(Tlen - 8 + pt) * Hdim + slice * 64 + pu * 4)
        = *(const float4*)&xout[1][pb][pt][pu * 4];

    // No CTA may exit while peers' bulk copies could still target it
    cluster_sync_asm();
}

// ---------------------------------------------------------------------------
extern "C" void kernel_launch(void* const* d_in, const int* in_sizes, int n_in,
                              void* d_out, int out_size)
{
    (void)in_sizes; (void)n_in; (void)out_size;
    const float* x    = (const float*)d_in[0];   // [32, 1024, 512]
    const float* Wih  = (const float*)d_in[1];   // [512, 512]
    const float* Whh  = (const float*)d_in[2];   // [512, 512]
    const float* bih  = (const float*)d_in[3];   // [512]
    const float* bhh  = (const float*)d_in[4];   // [512]
    const float* kern = (const float*)d_in[5];   // [4]

    float* out        = (float*)d_out;
    float* out_states = out;                                   // [32,1024,512]
    float* out_last   = out + (size_t)Bsz * Tlen * Hdim;       // [32,512]

    dim3 gg(Hdim / 128, (Bsz * Tlen) / 128);   // (4, 256)
    xproj_kernel<<<gg, 256>>>(x, Wih, bih, bhh);

    dim3 gr(8, 16);
    rnn_kernel<<<gr, 256>>>(Whh, kern, out_states, out_last);
}

// round 14
// speedup vs baseline: 1.3880x; 1.1048x over previous
#include <cuda_runtime.h>
#include <cuda_bf16.h>
#include <cstdint>

// Problem constants
#define Bsz 32
#define Tlen 1024
#define Idim 512
#define Hdim 512

// Scratch (device globals: no allocation allowed)
__device__ float g_xproj[(size_t)Bsz * Tlen * Hdim];                  // 64 MB
__device__ __align__(16) __nv_bfloat16 g_xh[(size_t)Bsz * Tlen * Idim];
__device__ __align__(16) __nv_bfloat16 g_xl[(size_t)Bsz * Tlen * Idim];
__device__ __align__(16) __nv_bfloat16 g_wh[(size_t)Hdim * Idim];
__device__ __align__(16) __nv_bfloat16 g_wl[(size_t)Hdim * Idim];

// ---------------------------------------------------------------------------
// packed f32x2 helpers (FFMA2 — ptxas never auto-fuses; PTX-only)
// ---------------------------------------------------------------------------
using u64 = unsigned long long;
__device__ __forceinline__ u64 pk2(float lo, float hi) {
    u64 r; asm("mov.b64 %0,{%1,%2};" : "=l"(r) : "f"(lo), "f"(hi)); return r;
}
__device__ __forceinline__ float2 upk2(u64 v) {
    float2 f; asm("mov.b64 {%0,%1},%2;" : "=f"(f.x), "=f"(f.y) : "l"(v)); return f;
}
__device__ __forceinline__ u64 fma2(u64 a, u64 b, u64 c) {
    u64 d; asm("fma.rn.f32x2 %0,%1,%2,%3;" : "=l"(d) : "l"(a), "l"(b), "l"(c)); return d;
}
__device__ __forceinline__ u64 add2(u64 a, u64 b) {
    u64 d; asm("add.rn.f32x2 %0,%1,%2;" : "=l"(d) : "l"(a), "l"(b)); return d;
}
__device__ __forceinline__ u64 mul2(u64 a, u64 b) {
    u64 d; asm("mul.rn.f32x2 %0,%1,%2;" : "=l"(d) : "l"(a), "l"(b)); return d;
}

__device__ __forceinline__ uint32_t s2u(const void* p) {
    uint32_t a;
    asm("{ .reg .u64 t; cvta.to.shared.u64 t, %1; cvt.u32.u64 %0, t; }"
        : "=r"(a) : "l"(p));
    return a;
}
__device__ __forceinline__ uint32_t mapa_rank(uint32_t laddr, uint32_t rank) {
    uint32_t r;
    asm("mapa.shared::cluster.u32 %0, %1, %2;" : "=r"(r) : "r"(laddr), "r"(rank));
    return r;
}
__device__ __forceinline__ void mbar_init(uint32_t mb, uint32_t cnt) {
    asm volatile("mbarrier.init.shared.b64 [%0], %1;" :: "r"(mb), "r"(cnt) : "memory");
}
__device__ __forceinline__ void mbar_arrive_expect_tx(uint32_t mb, uint32_t bytes) {
    asm volatile("mbarrier.arrive.expect_tx.shared.b64 _, [%0], %1;"
                 :: "r"(mb), "r"(bytes) : "memory");
}
__device__ __forceinline__ void mbar_wait_parity(uint32_t mb, uint32_t parity) {
    asm volatile(
        "{\n\t"
        ".reg .pred P;\n\t"
        "WLOOP_%=:\n\t"
        "mbarrier.try_wait.parity.acquire.cta.shared::cta.b64 P, [%0], %1, 0x989680;\n\t"
        "@P bra.uni WDONE_%=;\n\t"
        "bra.uni WLOOP_%=;\n\t"
        "WDONE_%=:\n\t"
        "}"
        :: "r"(mb), "r"(parity) : "memory");
}
__device__ __forceinline__ void bulk_dsmem(uint32_t dst, uint32_t src,
                                           uint32_t bytes, uint32_t rembar) {
    asm volatile(
        "cp.async.bulk.shared::cluster.shared::cta.mbarrier::complete_tx::bytes "
        "[%0], [%1], %2, [%3];"
        :: "r"(dst), "r"(src), "r"(bytes), "r"(rembar) : "memory");
}
__device__ __forceinline__ void fence_proxy_async_cta() {
    asm volatile("fence.proxy.async.shared::cta;" ::: "memory");
}
__device__ __forceinline__ void cluster_sync_asm() {
    asm volatile("barrier.cluster.arrive.aligned;" ::: "memory");
    asm volatile("barrier.cluster.wait.aligned;" ::: "memory");
}
__device__ __forceinline__ u64 shflx2(u64 v, int m) {
    float2 f = upk2(v);
    f.x = __shfl_xor_sync(0xFFFFFFFFu, f.x, m);
    f.y = __shfl_xor_sync(0xFFFFFFFFu, f.y, m);
    return pk2(f.x, f.y);
}
// Fast branch-free tanh (rel err ~1e-6, fine vs 1e-3 tolerance)
__device__ __forceinline__ float ftanh(float x) {
    float ax = fabsf(x);
    float e = __expf(-2.0f * ax);
    float r = __fdividef(1.0f - e, 1.0f + e);
    return copysignf(r, x);
}

// ---------------------------------------------------------------------------
// Kernel 0: split fp32 -> (bf16 hi, bf16 lo) for X (which=0) or Wih (which=1)
// ---------------------------------------------------------------------------
__global__ void split_bf16_kernel(const float* __restrict__ src, int n4, int which)
{
    int i = blockIdx.x * blockDim.x + threadIdx.x;
    if (i >= n4) return;
    __nv_bfloat16* hi = which ? g_wh : g_xh;
    __nv_bfloat16* lo = which ? g_wl : g_xl;
    float4 v = ((const float4*)src)[i];
    __nv_bfloat16 h0 = __float2bfloat16(v.x);
    __nv_bfloat16 h1 = __float2bfloat16(v.y);
    __nv_bfloat16 h2 = __float2bfloat16(v.z);
    __nv_bfloat16 h3 = __float2bfloat16(v.w);
    __nv_bfloat16 l0 = __float2bfloat16(v.x - __bfloat162float(h0));
    __nv_bfloat16 l1 = __float2bfloat16(v.y - __bfloat162float(h1));
    __nv_bfloat16 l2 = __float2bfloat16(v.z - __bfloat162float(h2));
    __nv_bfloat16 l3 = __float2bfloat16(v.w - __bfloat162float(h3));
    __nv_bfloat162* hp = (__nv_bfloat162*)(hi + 4 * (size_t)i);
    __nv_bfloat162* lp = (__nv_bfloat162*)(lo + 4 * (size_t)i);
    hp[0] = __halves2bfloat162(h0, h1);
    hp[1] = __halves2bfloat162(h2, h3);
    lp[0] = __halves2bfloat162(l0, l1);
    lp[1] = __halves2bfloat162(l2, l3);
}

// ---------------------------------------------------------------------------
// Kernel 1: xproj via mma.sync.m16n8k16.bf16 (split-bf16, 3-product fp32
//   emulation; lowers to HMMA on sm_103 — tcgen05 is NOT available through
//   this harness's compute_103 PTX stage).
//   CTA tile 128m x 128n, K chunked by 64, cp.async double-buffered smem,
//   pad-72 rows => all fragment loads bank-conflict-free (bank = 4*row+quad).
//   Warp grid 2(m) x 4(n); warp tile 64x32; 64 fp32 accums/thread.
// ---------------------------------------------------------------------------
#define MMA_BF16(d, a, b0_, b1_) \
    asm volatile( \
        "mma.sync.aligned.m16n8k16.row.col.f32.bf16.bf16.f32 " \
        "{%0,%1,%2,%3}, {%4,%5,%6,%7}, {%8,%9}, {%0,%1,%2,%3};" \
        : "+f"((d)[0]), "+f"((d)[1]), "+f"((d)[2]), "+f"((d)[3]) \
        : "r"((a)[0]), "r"((a)[1]), "r"((a)[2]), "r"((a)[3]), \
          "r"(b0_), "r"(b1_))

static constexpr int XPADB = 144;                   // 72 bf16 per row, bytes
static constexpr int MAT_BYTES = 128 * XPADB;       // 18432
static constexpr int BUF_BYTES = 4 * MAT_BYTES;     // 73728
static constexpr int XS_TOTAL  = 2 * BUF_BYTES;     // 147456

__global__ void __launch_bounds__(256, 1)
xproj_mma_kernel(const float* __restrict__ bih, const float* __restrict__ bhh)
{
    extern __shared__ __align__(128) char xsm[];
    const int tid  = threadIdx.x;
    const int lane = tid & 31;
    const int w    = tid >> 5;
    const int wm   = w >> 2;          // 0..1 (m 64-block)
    const int wn   = w & 3;           // 0..3 (n 32-block)
    const int m0 = blockIdx.y * 128;
    const int h0 = blockIdx.x * 128;
    const uint32_t sb = s2u(xsm);

    const int lr = lane >> 2;         // fragment row 0..7
    const int lc = (lane & 3) * 2;    // fragment k/col pair base

    auto issue_chunk = [&](int buf, int k0) {
#pragma unroll
        for (int q = 0; q < 16; ++q) {
            int idx = tid + 256 * q;
            int mat = idx >> 10;          // 0=xh 1=xl 2=wh 3=wl
            int it  = idx & 1023;
            int r   = it >> 3;
            int c8  = (it & 7) * 8;
            const __nv_bfloat16* src;
            if (mat == 0)      src = g_xh + (size_t)(m0 + r) * Idim + k0 + c8;
            else if (mat == 1) src = g_xl + (size_t)(m0 + r) * Idim + k0 + c8;
            else if (mat == 2) src = g_wh + (size_t)(h0 + r) * Idim + k0 + c8;
            else               src = g_wl + (size_t)(h0 + r) * Idim + k0 + c8;
            uint32_t dst = sb + (uint32_t)(buf * BUF_BYTES + mat * MAT_BYTES
                                           + r * XPADB + c8 * 2);
            asm volatile("cp.async.cg.shared.global [%0], [%1], 16;"
                         :: "r"(dst), "l"(src));
        }
        asm volatile("cp.async.commit_group;" ::: "memory");
    };

    issue_chunk(0, 0);

    float acc[4][4][4];
#pragma unroll
    for (int i = 0; i < 4; ++i)
#pragma unroll
        for (int j = 0; j < 4; ++j)
#pragma unroll
            for (int v = 0; v < 4; ++v) acc[i][j][v] = 0.f;

    asm volatile("cp.async.wait_group 0;" ::: "memory");
    __syncthreads();

    for (int ch = 0; ch < 8; ++ch) {
        const int buf = ch & 1;
        if (ch < 7) issue_chunk(buf ^ 1, (ch + 1) * 64);

        const char* A0 = xsm + buf * BUF_BYTES;        // xh
        const char* A1 = A0 + MAT_BYTES;               // xl
        const char* B0 = A0 + 2 * MAT_BYTES;           // wh
        const char* B1 = A0 + 3 * MAT_BYTES;           // wl

#pragma unroll
        for (int kk = 0; kk < 4; ++kk) {
            const int kb2 = (kk * 16 + lc) * 2;        // byte offset in row
            uint32_t aH[4][4], aL[4][4];
#pragma unroll
            for (int mt = 0; mt < 4; ++mt) {
                const int rb = wm * 64 + mt * 16 + lr;
                const char* pH = A0 + rb * XPADB + kb2;
                const char* pL = A1 + rb * XPADB + kb2;
                aH[mt][0] = *(const uint32_t*)(pH);
                aH[mt][1] = *(const uint32_t*)(pH + 8 * XPADB);
                aH[mt][2] = *(const uint32_t*)(pH + 16);
                aH[mt][3] = *(const uint32_t*)(pH + 8 * XPADB + 16);
                aL[mt][0] = *(const uint32_t*)(pL);
                aL[mt][1] = *(const uint32_t*)(pL + 8 * XPADB);
                aL[mt][2] = *(const uint32_t*)(pL + 16);
                aL[mt][3] = *(const uint32_t*)(pL + 8 * XPADB + 16);
            }
#pragma unroll
            for (int nt = 0; nt < 4; ++nt) {
                const int hb = wn * 32 + nt * 8 + lr;
                const char* qH = B0 + hb * XPADB + kb2;
                const char* qL = B1 + hb * XPADB + kb2;
                uint32_t bH0 = *(const uint32_t*)(qH);
                uint32_t bH1 = *(const uint32_t*)(qH + 16);
                uint32_t bL0 = *(const uint32_t*)(qL);
                uint32_t bL1 = *(const uint32_t*)(qL + 16);
#pragma unroll
                for (int mt = 0; mt < 4; ++mt) {
                    MMA_BF16(acc[mt][nt], aH[mt], bH0, bH1);   // xh*wh
                    MMA_BF16(acc[mt][nt], aH[mt], bL0, bL1);   // xh*wl
                    MMA_BF16(acc[mt][nt], aL[mt], bH0, bH1);   // xl*wh
                }
            }
        }

        if (ch < 7) {
            asm volatile("cp.async.wait_group 0;" ::: "memory");
            __syncthreads();
        }
    }

    // Epilogue: fused bias, direct float2 stores (32B-sector aligned)
#pragma unroll
    for (int nt = 0; nt < 4; ++nt) {
        const int c = h0 + wn * 32 + nt * 8 + lc;
        const float bs0 = bih[c] + bhh[c];
        const float bs1 = bih[c + 1] + bhh[c + 1];
#pragma unroll
        for (int mt = 0; mt < 4; ++mt) {
            const int r = m0 + wm * 64 + mt * 16 + lr;
            float2 v0 = make_float2(acc[mt][nt][0] + bs0, acc[mt][nt][1] + bs1);
            float2 v1 = make_float2(acc[mt][nt][2] + bs0, acc[mt][nt][3] + bs1);
            *(float2*)(g_xproj + (size_t)r * Hdim + c) = v0;
            *(float2*)(g_xproj + (size_t)(r + 8) * Hdim + c) = v1;
        }
    }
}

// ---------------------------------------------------------------------------
// Kernel 2: the recurrence — all-to-all of M-partials via bulk DSMEM engine.
//   BYTE-IDENTICAL to the measured best (rounds 9/11).
// ---------------------------------------------------------------------------
__global__ void __launch_bounds__(256, 1) __cluster_dims__(8, 1, 1)
rnn_kernel(const float* __restrict__ Whh,   // [512, 512]
           const float* __restrict__ kern,  // [4]
           float* __restrict__ out_states,  // [B, T, H]
           float* __restrict__ out_last)    // [B, H]
{
    __shared__ __align__(16) float arr[2][8][128];    // 8KB [slot][src][swz 512B]
    __shared__ __align__(16) float stg[2][8][128];    // 8KB [slot][warp][512B]
    __shared__ __align__(16) float hloc[2][64];       // h_t[own rows], batch-major
    __shared__ __align__(16) float xs[2][2][8][64];   // 8KB xproj stage
    __shared__ __align__(16) float xout[2][2][8][64]; // 8KB output stage (dbuf)
    __shared__ __align__(8)  u64 mbars[2];

    const int tid   = threadIdx.x;
    const int lane  = tid & 31;
    const int w     = tid >> 5;            // warp id == destination peer
    const int slice = blockIdx.x;          // cluster rank 0..7
    const int grp   = blockIdx.y;          // 0..15
    const int b0    = grp * 2;

    u64 wR0[32], wR1[32];
    {
        const float* r0p = Whh + (size_t)(64 * w + 2 * lane) * Hdim + 64 * slice;
        const float* r1p = r0p + Hdim;
#pragma unroll
        for (int m = 0; m < 16; ++m) {
            ulonglong2 u0 = *(const ulonglong2*)(r0p + 4 * m);
            ulonglong2 u1 = *(const ulonglong2*)(r1p + 4 * m);
            wR0[2 * m] = u0.x; wR0[2 * m + 1] = u0.y;
            wR1[2 * m] = u1.x; wR1[2 * m + 1] = u1.y;
        }
    }
    const u64 kk0 = pk2(kern[0], kern[0]), kk1 = pk2(kern[1], kern[1]);
    const u64 kk2 = pk2(kern[2], kern[2]), kk3 = pk2(kern[3], kern[3]);

    const uint32_t mb0 = s2u(&mbars[0]);
    if (tid == 0) {
        mbar_init(mb0, 1);
        mbar_init(mb0 + 8, 1);
        mbar_arrive_expect_tx(mb0, 7 * 512);
        mbar_arrive_expect_tx(mb0 + 8, 7 * 512);
    }

    const uint32_t arr_b = s2u(arr);
    const uint32_t dst_b = mapa_rank(arr_b, w) + (uint32_t)(slice * 512);
    const uint32_t bar_b = mapa_rank(mb0, w);

    cluster_sync_asm();

    const int pb  = tid >> 7;
    const int pt  = (tid >> 4) & 7;
    const int pu  = tid & 15;
    const float* xsrc = g_xproj + (size_t)(b0 + pb) * Tlen * Hdim
                        + (size_t)pt * Hdim + slice * 64 + pu * 4;
    *(float4*)&xs[0][pb][pt][pu * 4] = *(const float4*)(xsrc);
    float4 xpre = *(const float4*)(xsrc + 8 * Hdim);
    __syncthreads();

    const int row  = tid >> 2;
    const int quad = tid & 3;

    u64 ring0 = 0ull, ring1 = 0ull, ring2 = 0ull;

    const char* arrc = (const char*)arr;

    for (int t = 0; t < Tlen; ++t) {
        if ((t & 7) == 0) {
            int g = t >> 3;
            *(float4*)&xs[(g + 1) & 1][pb][pt][pu * 4] = xpre;
            if (t + 16 < Tlen)
                xpre = *(const float4*)(xsrc + (size_t)(t + 16) * Hdim);
            if (t > 0) {
                *(float4*)(out_states + (size_t)(b0 + pb) * Tlen * Hdim
                           + (size_t)(t - 8 + pt) * Hdim + slice * 64 + pu * 4)
                    = *(const float4*)&xout[(g - 1) & 1][pb][pt][pu * 4];
            }
        }

        u64 Mt1 = 0ull;
        if (t > 0) {
            const uint32_t bar = mb0 + ((t - 1) & 1) * 8;
            mbar_wait_parity(bar, ((t - 1) >> 1) & 1);
            if (tid == 0)
                mbar_arrive_expect_tx(bar, 7 * 512);

            const char* ab = arrc + ((t - 1) & 1) * 4096;
            const int s0 = 2 * quad, s1 = 2 * quad + 1;
            const int pbk = row >> 1, rb = (row & 1) * 8;
            u64 v0 = *(const u64*)(ab + s0 * 512 + (((pbk + 5 * s0) & 31) * 16 + rb));
            u64 v1 = *(const u64*)(ab + s1 * 512 + (((pbk + 5 * s1) & 31) * 16 + rb));
            u64 m = add2(v0, v1);
            m = add2(m, shflx2(m, 1));
            m = add2(m, shflx2(m, 2));
            Mt1 = m;
        }

        u64 rr = fma2(kk0, Mt1, fma2(kk1, ring0, fma2(kk2, ring1, mul2(kk3, ring2))));
        ring2 = ring1; ring1 = ring0; ring0 = Mt1;

        if (quad < 2) {
            float2 rf = upk2(rr);
            float pre = (quad == 0) ? rf.x : rf.y;
            float val = ftanh(pre + xs[(t >> 3) & 1][quad][t & 7][row]);
            hloc[quad][row] = val;
            xout[(t >> 3) & 1][quad][t & 7][row] = val;
            if (t == Tlen - 1)
                out_last[(size_t)(b0 + quad) * Hdim + slice * 64 + row] = val;
        }

        __syncthreads();

        if (t < Tlen - 1) {
            u64 aA0 = 0ull, cA0 = 0ull, aA1 = 0ull, cA1 = 0ull;
            u64 aB0 = 0ull, cB0 = 0ull, aB1 = 0ull, cB1 = 0ull;
#pragma unroll
            for (int m = 0; m < 16; ++m) {
                ulonglong2 h0 = *(const ulonglong2*)&hloc[0][4 * m];
                ulonglong2 h1 = *(const ulonglong2*)&hloc[1][4 * m];
                aA0 = fma2(wR0[2 * m],     h0.x, aA0);
                cA0 = fma2(wR0[2 * m + 1], h0.y, cA0);
                aA1 = fma2(wR0[2 * m],     h1.x, aA1);
                cA1 = fma2(wR0[2 * m + 1], h1.y, cA1);
                aB0 = fma2(wR1[2 * m],     h0.x, aB0);
                cB0 = fma2(wR1[2 * m + 1], h0.y, cB0);
                aB1 = fma2(wR1[2 * m],     h1.x, aB1);
                cB1 = fma2(wR1[2 * m + 1], h1.y, cB1);
            }
            float2 fA0 = upk2(add2(aA0, cA0));
            float2 fA1 = upk2(add2(aA1, cA1));
            float2 fB0 = upk2(add2(aB0, cB0));
            float2 fB1 = upk2(add2(aB1, cB1));
            float4 o = make_float4(fA0.x + fA0.y, fA1.x + fA1.y,
                                   fB0.x + fB0.y, fB1.x + fB1.y);
            float* dstp = (w == slice) ? &arr[t & 1][slice][0]
                                       : &stg[t & 1][w][0];
            *(float4*)(dstp + ((lane + 5 * slice) & 31) * 4) = o;
            __syncwarp();
            if (w != slice && lane == 0) {
                fence_proxy_async_cta();
                bulk_dsmem(dst_b + (uint32_t)((t & 1) * 4096),
                           s2u(&stg[t & 1][w][0]), 512,
                           bar_b + (uint32_t)((t & 1) * 8));
            }
        }

        __syncthreads();
    }

    *(float4*)(out_states + (size_t)(b0 + pb) * Tlen * Hdim
               + (size_t)(Tlen - 8 + pt) * Hdim + slice * 64 + pu * 4)
        = *(const float4*)&xout[1][pb][pt][pu * 4];

    cluster_sync_asm();
}

// ---------------------------------------------------------------------------
extern "C" void kernel_launch(void* const* d_in, const int* in_sizes, int n_in,
                              void* d_out, int out_size)
{
    (void)in_sizes; (void)n_in; (void)out_size;
    const float* x    = (const float*)d_in[0];   // [32, 1024, 512]
    const float* Wih  = (const float*)d_in[1];   // [512, 512]
    const float* Whh  = (const float*)d_in[2];   // [512, 512]
    const float* bih  = (const float*)d_in[3];   // [512]
    const float* bhh  = (const float*)d_in[4];   // [512]
    const float* kern = (const float*)d_in[5];   // [4]

    float* out        = (float*)d_out;
    float* out_states = out;                                   // [32,1024,512]
    float* out_last   = out + (size_t)Bsz * Tlen * Hdim;       // [32,512]

    // 0) Split X and Wih into bf16 hi/lo
    int nx4 = (Bsz * Tlen * Idim) / 4;
    int nw4 = (Hdim * Idim) / 4;
    split_bf16_kernel<<<(nx4 + 255) / 256, 256>>>(x, nx4, 0);
    split_bf16_kernel<<<(nw4 + 255) / 256, 256>>>(Wih, nw4, 1);

    // 1) Input projection on HMMA tensor cores (split-bf16, fp32 accumulate)
    cudaFuncSetAttribute(xproj_mma_kernel,
                         cudaFuncAttributeMaxDynamicSharedMemorySize, XS_TOTAL);
    dim3 gx(Hdim / 128, (Bsz * Tlen) / 128);   // (4, 256)
    xproj_mma_kernel<<<gx, 256, XS_TOTAL>>>(bih, bhh);

    // 2) Sequential recurrence: 16 clusters of 8 CTAs
    dim3 gr(8, 16);
    rnn_kernel<<<gr, 256>>>(Whh, kern, out_states, out_last);
}